// round 17
// baseline (speedup 1.0000x reference)
#include <cuda_runtime.h>
#include <cuda_fp16.h>
#include <cuda_fp8.h>
#include <cstdint>

#define G    64
#define FOLD 256
#define HID  128
#define TM   128   // rows per tile
#define NCH  4     // k-chunks of 64 (K=256)
#define NTHR 256
#define WSCALE   64.0f
#define INV_WS   0.015625f

// Scratch (device globals).
__device__ float g_num[3 * G * FOLD];
__device__ float g_den[3 * G];
// W1 transposed to [n=128][k=256] e4m3, scaled by 64, per pool.
__device__ __align__(16) uint8_t g_w1e[3 * HID * FOLD];

// Smem layout (bytes). fp8 rows are 64B, packed 2 logical rows per 128B.
#define OFF_AS    0        // A: 128m x 64k fp8 = 8192
#define OFF_BS    8192     // B: 128n x 64k fp8 = 8192
#define OFF_ACCS  16384    // 64 x 256 f32 = 65536
#define OFF_PART  81920    // 2 x 128 f32  = 1024
#define OFF_ES    82944    // 128 f32      = 512
#define OFF_SGS   83456    // 128 int      = 512
#define OFF_DENS  83968    // 64 f32       = 256
#define OFF_B1S   84224    // 128 f32      = 512
#define OFF_W2S   84736    // 128 f32      = 512
#define SMEM_SZ   85248

// ---------------------------------------------------------------------------
__global__ void prep_kernel(const float* __restrict__ pa,
                            const float* __restrict__ la,
                            const float* __restrict__ ca) {
    int i = blockIdx.x * blockDim.x + threadIdx.x;
    if (i < 3 * HID * FOLD) {
        int p = i / (HID * FOLD);
        int j = i - p * (HID * FOLD);
        int n = j >> 8;          // 0..127
        int k = j & 255;         // 0..255
        const float* W = (p == 0) ? pa : (p == 1) ? la : ca;
        __nv_fp8_e4m3 v(W[k * HID + n] * WSCALE);
        g_w1e[i] = *reinterpret_cast<uint8_t*>(&v);
    }
    if (i < 3 * G * FOLD) g_num[i] = 0.f;
    if (i < 3 * G)        g_den[i] = 0.f;
}

__device__ __forceinline__ uint32_t smem_u32(const void* p) {
    return (uint32_t)__cvta_generic_to_shared(p);
}
// Pack 4 floats -> 4 e4m3 bytes (byte0 = f0).
__device__ __forceinline__ uint32_t pack_e4m3x4(float f0, float f1, float f2, float f3) {
    uint32_t lo, hi;
    asm("{\n\t.reg .b16 t;\n\tcvt.rn.satfinite.e4m3x2.f32 t, %1, %2;\n\t"
        "cvt.u32.u16 %0, t;\n\t}" : "=r"(lo) : "f"(f1), "f"(f0));
    asm("{\n\t.reg .b16 t;\n\tcvt.rn.satfinite.e4m3x2.f32 t, %1, %2;\n\t"
        "cvt.u32.u16 %0, t;\n\t}" : "=r"(hi) : "f"(f3), "f"(f2));
    return lo | (hi << 16);
}
// fp8 tile addressing: 128 logical rows x 64B packed into 64 x 128B physical
// rows; 16B-unit column swizzled by physical row.
__device__ __forceinline__ uint32_t fp8_addr(int r, int kc) {
    int p   = r >> 1;
    int col = (r & 1) * 4 + kc;      // 0..7
    return (uint32_t)(p * 128 + ((col ^ (p & 7)) << 4));
}

// ---------------------------------------------------------------------------
// Fused scores + attention-pool (r8 champion with FP8 e4m3 GEMM).
// Persistent blocks, m128 tiles, 2 CTA/SM. e4m3 inputs, f16 accumulation,
// W1 pre-scaled x64 (epilogue multiplies by 1/64). A loaded fp32 -> e4m3 in
// registers -> STS.128; B staged via raw cp.async from pre-converted e4m3 W1
// (L2-resident). Pooling: col-owner fp32 from global, 16-row LDG batches,
// smem accs (no atomics in loop), smem-atomic denominators.
__global__ __launch_bounds__(NTHR, 2) void fused_kernel(
    const float* __restrict__ x, int N,
    const int* __restrict__ batch, const int* __restrict__ ci0,
    const int* __restrict__ lb, int indirect, int pool,
    const float* __restrict__ b1, const float* __restrict__ W2,
    const float* __restrict__ b2)
{
    extern __shared__ char smem[];
    char*  As   = smem + OFF_AS;
    char*  Bs   = smem + OFF_BS;
    float* accs = (float*)(smem + OFF_ACCS);
    float* part = (float*)(smem + OFF_PART);
    float* e_s  = (float*)(smem + OFF_ES);
    int*   sg_s = (int*)  (smem + OFF_SGS);
    float* dens = (float*)(smem + OFF_DENS);
    float* b1s  = (float*)(smem + OFF_B1S);
    float* w2s  = (float*)(smem + OFF_W2S);

    const uint8_t* W1e = g_w1e + (size_t)pool * (HID * FOLD);

    const int tid    = threadIdx.x;
    const int lane   = tid & 31;
    const int warp   = tid >> 5;
    const int warp_m = warp >> 1;       // 0..3  (m32 groups)
    const int wn     = warp & 1;        // 0..1  (n64 groups)
    const int m0     = warp_m * 32;

    for (int i = tid; i < G * FOLD; i += NTHR) accs[i] = 0.f;
    if (tid < G) dens[tid] = 0.f;
    if (tid < HID) { b1s[tid] = b1[tid]; w2s[tid] = W2[tid]; }
    const float b2v = b2[0];
    __syncthreads();

    const uint32_t as_base = smem_u32(As);
    const uint32_t bs_base = smem_u32(Bs);
    const int ntiles = (N + TM - 1) / TM;

    for (int tile = blockIdx.x; tile < ntiles; tile += gridDim.x) {
        const int row0 = tile * TM;

        // f16 accumulators: 2 regs per m16n8 tile
        uint32_t accu[2][8][2];
#pragma unroll
        for (int mi = 0; mi < 2; mi++)
#pragma unroll
            for (int ni = 0; ni < 8; ni++) {
                accu[mi][ni][0] = 0u;
                accu[mi][ni][1] = 0u;
            }

        // A raw prefetch: per chunk each thread owns 2 16B fp8 units =
        // 32 fp32 elements = 8 float4.
        float4 araw[8];
        auto lda = [&](int kt) {
#pragma unroll
            for (int j = 0; j < 2; j++) {
                int u  = tid + j * 256;      // 512 units (128 rows x 4)
                int r  = u >> 2;
                int kc = u & 3;
                int grow = row0 + r;
                if (grow < N) {
                    const float4* p = (const float4*)(x + (size_t)grow * FOLD + kt * 64 + kc * 16);
#pragma unroll
                    for (int q = 0; q < 4; q++) araw[j * 4 + q] = p[q];
                } else {
#pragma unroll
                    for (int q = 0; q < 4; q++)
                        araw[j * 4 + q] = make_float4(0.f, 0.f, 0.f, 0.f);
                }
            }
        };
        auto sta = [&]() {
#pragma unroll
            for (int j = 0; j < 2; j++) {
                int u  = tid + j * 256;
                int r  = u >> 2;
                int kc = u & 3;
                uint4 v;
                v.x = pack_e4m3x4(araw[j*4+0].x, araw[j*4+0].y, araw[j*4+0].z, araw[j*4+0].w);
                v.y = pack_e4m3x4(araw[j*4+1].x, araw[j*4+1].y, araw[j*4+1].z, araw[j*4+1].w);
                v.z = pack_e4m3x4(araw[j*4+2].x, araw[j*4+2].y, araw[j*4+2].z, araw[j*4+2].w);
                v.w = pack_e4m3x4(araw[j*4+3].x, araw[j*4+3].y, araw[j*4+3].z, araw[j*4+3].w);
                *(uint4*)(As + fp8_addr(r, kc)) = v;
            }
        };

        lda(0);   // prologue A prefetch

#pragma unroll 1
        for (int kt = 0; kt < NCH; kt++) {
            __syncthreads();   // mma(kt-1) done reading As/Bs (kt=0: pooling done)

            // B(kt): raw cp.async from e4m3 W1 (issued first for max overlap)
#pragma unroll
            for (int j = 0; j < 2; j++) {
                int u  = tid + j * 256;      // 512 16B-units
                int n  = u >> 2;
                int kc = u & 3;
                uint32_t dst = bs_base + fp8_addr(n, kc);
                const char* src = (const char*)W1e + (size_t)n * 256 + kt * 64 + kc * 16;
                asm volatile("cp.async.cg.shared.global [%0], [%1], 16;"
                             :: "r"(dst), "l"(src));
            }
            asm volatile("cp.async.commit_group;");

            sta();                           // A(kt) from prefetched regs
            if (kt + 1 < NCH) lda(kt + 1);   // A(kt+1) LDG hides under mma

            asm volatile("cp.async.wait_group 0;");
            __syncthreads();                 // tiles published

#pragma unroll
            for (int ks = 0; ks < 2; ks++) { // two k32 steps per k64 chunk
                uint32_t af[2][4];
#pragma unroll
                for (int mi = 0; mi < 2; mi++) {
                    int r  = m0 + mi * 16 + (lane & 7) + ((lane >> 3) & 1) * 8;
                    int kc = ks * 2 + (lane >> 4);
                    uint32_t addr = as_base + fp8_addr(r, kc);
                    asm volatile(
                        "ldmatrix.sync.aligned.m8n8.x4.shared.b16 {%0,%1,%2,%3}, [%4];"
                        : "=r"(af[mi][0]), "=r"(af[mi][1]), "=r"(af[mi][2]), "=r"(af[mi][3])
                        : "r"(addr));
                }
                uint32_t bf[8][2];
#pragma unroll
                for (int jj = 0; jj < 4; jj++) {  // each x4 covers 2 n8-groups
                    int g  = lane >> 3;           // 0..3
                    int n  = wn * 64 + jj * 16 + (g >> 1) * 8 + (lane & 7);
                    int kc = ks * 2 + (g & 1);
                    uint32_t addr = bs_base + fp8_addr(n, kc);
                    asm volatile(
                        "ldmatrix.sync.aligned.m8n8.x4.shared.b16 {%0,%1,%2,%3}, [%4];"
                        : "=r"(bf[jj*2][0]), "=r"(bf[jj*2][1]),
                          "=r"(bf[jj*2+1][0]), "=r"(bf[jj*2+1][1])
                        : "r"(addr));
                }
#pragma unroll
                for (int mi = 0; mi < 2; mi++)
#pragma unroll
                    for (int ni = 0; ni < 8; ni++)
                        asm volatile(
                            "mma.sync.aligned.m16n8k32.row.col.f16.e4m3.e4m3.f16 "
                            "{%0,%1}, {%2,%3,%4,%5}, {%6,%7}, {%0,%1};"
                            : "+r"(accu[mi][ni][0]), "+r"(accu[mi][ni][1])
                            : "r"(af[mi][0]), "r"(af[mi][1]), "r"(af[mi][2]), "r"(af[mi][3]),
                              "r"(bf[ni][0]), "r"(bf[ni][1]));
            }
        }

        // ---- epilogue: unscale (x 1/64), relu + 2nd linear, n64 partials
#pragma unroll
        for (int mi = 0; mi < 2; mi++) {
            float p1 = 0.f, p2 = 0.f;
            const int cb = (lane & 3) * 2;
#pragma unroll
            for (int ni = 0; ni < 8; ni++) {
                int c = wn * 64 + ni * 8 + cb;
                float w0 = w2s[c], w1v = w2s[c + 1];
                float q0 = b1s[c], q1 = b1s[c + 1];
                float2 f0 = __half22float2(*(__half2*)&accu[mi][ni][0]);  // rows r
                float2 f1 = __half22float2(*(__half2*)&accu[mi][ni][1]);  // rows r+8
                p1 += fmaxf(fmaf(f0.x, INV_WS, q0), 0.f) * w0
                    + fmaxf(fmaf(f0.y, INV_WS, q1), 0.f) * w1v;
                p2 += fmaxf(fmaf(f1.x, INV_WS, q0), 0.f) * w0
                    + fmaxf(fmaf(f1.y, INV_WS, q1), 0.f) * w1v;
            }
            p1 += __shfl_xor_sync(0xffffffffu, p1, 1);
            p1 += __shfl_xor_sync(0xffffffffu, p1, 2);
            p2 += __shfl_xor_sync(0xffffffffu, p2, 1);
            p2 += __shfl_xor_sync(0xffffffffu, p2, 2);
            if ((lane & 3) == 0) {
                int rl = m0 + mi * 16 + (lane >> 2);
                part[wn * 128 + rl]     = p1;
                part[wn * 128 + rl + 8] = p2;
            }
        }
        __syncthreads();

        if (tid < TM) {
            int row = row0 + tid;
            if (row < N) {
                float s = part[tid] + part[128 + tid] + b2v;
                float e = __expf(s);
                int  sg = indirect ? __ldg(lb + __ldg(ci0 + row)) : __ldg(batch + row);
                e_s[tid]  = e;
                sg_s[tid] = sg;
                atomicAdd(dens + sg, e);   // <=2-way contention, smem atomics
            } else {
                e_s[tid]  = 0.f;
                sg_s[tid] = 0;
            }
        }
        __syncthreads();

        // ---- pooling: thread owns column tid (exclusive -> non-atomic +=),
        // 16-row LDG batches: deep memory-level parallelism. x re-read L2-hot.
        const int rows = min(TM, N - row0);
        {
            const int c = tid;
            int   cur = sg_s[0];
            float a   = 0.f;
            int r = 0;
            for (; r + 16 <= rows; r += 16) {
                float xv[16];
#pragma unroll
                for (int j = 0; j < 16; j++)
                    xv[j] = __ldg(x + (size_t)(row0 + r + j) * FOLD + c);
#pragma unroll
                for (int j = 0; j < 16; j++) {
                    int   sg = sg_s[r + j];
                    float ev = e_s[r + j];
                    if (sg != cur) { accs[cur * FOLD + c] += a; a = 0.f; cur = sg; }
                    a = fmaf(ev, xv[j], a);
                }
            }
            for (; r < rows; ++r) {
                int   sg = sg_s[r];
                float ev = e_s[r];
                float xv = __ldg(x + (size_t)(row0 + r) * FOLD + c);
                if (sg != cur) { accs[cur * FOLD + c] += a; a = 0.f; cur = sg; }
                a = fmaf(ev, xv, a);
            }
            accs[cur * FOLD + c] += a;
        }
    }

    __syncthreads();
    float* num = g_num + pool * G * FOLD;
    for (int i = tid; i < G * FOLD; i += NTHR) {
        float v = accs[i];
        if (v != 0.f) atomicAdd(num + i, v);
    }
    if (tid < G && dens[tid] != 0.f) atomicAdd(g_den + pool * G + tid, dens[tid]);
}

// ---------------------------------------------------------------------------
__global__ __launch_bounds__(256) void mlp_kernel(
    const float* __restrict__ W1, const float* __restrict__ b1,
    const float* __restrict__ W2, const float* __restrict__ b2,
    const float* __restrict__ oW, const float* __restrict__ ob,
    float* __restrict__ out)
{
    __shared__ float comb[3 * FOLD];
    __shared__ float h1s[FOLD];
    __shared__ float h2s[HID];
    __shared__ float red[4];

    const int g = blockIdx.x, t = threadIdx.x;

    for (int i = t; i < 3 * FOLD; i += 256) {
        int p = i >> 8, cc = i & 255;
        comb[i] = g_num[(p * G + g) * FOLD + cc] / g_den[p * G + g];
    }
    __syncthreads();

    float h = b1[t];
    for (int k = 0; k < 3 * FOLD; k++)
        h = fmaf(comb[k], W1[(size_t)k * FOLD + t], h);
    h1s[t] = fmaxf(h, 0.f);
    __syncthreads();

    if (t < HID) {
        float h2 = b2[t];
        for (int k = 0; k < FOLD; k++)
            h2 = fmaf(h1s[k], W2[(size_t)k * HID + t], h2);
        h2s[t] = fmaxf(h2, 0.f);
    }
    __syncthreads();

    if (t < HID) {
        float v = h2s[t] * oW[t];
#pragma unroll
        for (int off = 16; off > 0; off >>= 1)
            v += __shfl_down_sync(0xffffffffu, v, off);
        if ((t & 31) == 0) red[t >> 5] = v;
    }
    __syncthreads();
    if (t == 0) out[g] = red[0] + red[1] + red[2] + red[3] + ob[0];
}

// ---------------------------------------------------------------------------
extern "C" void kernel_launch(void* const* d_in, const int* in_sizes, int n_in,
                              void* d_out, int out_size)
{
    const float* rec   = (const float*)d_in[0];
    const float* lig   = (const float*)d_in[1];
    const float* cross = (const float*)d_in[2];
    const int*   cidx  = (const int*)d_in[3];
    const int*   pb    = (const int*)d_in[4];
    const int*   lb    = (const int*)d_in[5];
    const float* paW1 = (const float*)d_in[7];
    const float* pab1 = (const float*)d_in[8];
    const float* paW2 = (const float*)d_in[9];
    const float* pab2 = (const float*)d_in[10];
    const float* laW1 = (const float*)d_in[11];
    const float* lab1 = (const float*)d_in[12];
    const float* laW2 = (const float*)d_in[13];
    const float* lab2 = (const float*)d_in[14];
    const float* caW1 = (const float*)d_in[15];
    const float* cab1 = (const float*)d_in[16];
    const float* caW2 = (const float*)d_in[17];
    const float* cab2 = (const float*)d_in[18];
    const float* mW1  = (const float*)d_in[19];
    const float* mb1  = (const float*)d_in[20];
    const float* mW2  = (const float*)d_in[21];
    const float* mb2  = (const float*)d_in[22];
    const float* oW   = (const float*)d_in[23];
    const float* ob   = (const float*)d_in[24];

    float* out = (float*)d_out;

    const int Np = in_sizes[0] / FOLD;
    const int Nl = in_sizes[1] / FOLD;
    const int Nc = in_sizes[2] / FOLD;

    static bool attr_done = false;
    if (!attr_done) {
        cudaFuncSetAttribute(fused_kernel,
                             cudaFuncAttributeMaxDynamicSharedMemorySize, SMEM_SZ);
        attr_done = true;
    }

    prep_kernel<<<(3 * HID * FOLD + 255) / 256, 256>>>(paW1, laW1, caW1);

    const int maxb = 296;   // 2 CTA/SM x 148 SMs
    int gp = min((Np + TM - 1) / TM, maxb);
    int gl = min((Nl + TM - 1) / TM, maxb);
    int gc = min((Nc + TM - 1) / TM, maxb);

    fused_kernel<<<gp, NTHR, SMEM_SZ>>>(rec, Np, pb, nullptr, nullptr, 0, 0,
                                        pab1, paW2, pab2);
    fused_kernel<<<gl, NTHR, SMEM_SZ>>>(lig, Nl, lb, nullptr, nullptr, 0, 1,
                                        lab1, laW2, lab2);
    fused_kernel<<<gc, NTHR, SMEM_SZ>>>(cross, Nc, nullptr, cidx, lb, 1, 2,
                                        cab1, caW2, cab2);

    mlp_kernel<<<G, 256>>>(mW1, mb1, mW2, mb2, oW, ob, out);
}